// round 15
// baseline (speedup 1.0000x reference)
#include <cuda_runtime.h>
#include <cuda_fp16.h>
#include <cstdint>

#define N_NODES 50000
#define N_EDGES 800000
#define HALF_E (N_EDGES / 2)
#define CH 64
#define CH4 16
#define OUT_ELEMS (N_NODES * CH)
#define GX 391                            // ceil(50000/128)
#define ZERO_FLOAT4 (OUT_ELEMS * 2 / 4)   // 1,600,000
#define PITCH 72                          // smem pitch in halves (conflict-free LDSM)

// ---- scratch (device globals; no allocation allowed) ----
// support tensors in fp16: [branch][node*16 + chunk], chunk = 4 halves (8B)
__device__ uint2 g_suph[2][N_NODES * CH4];

// ---------------------------------------------------------------------------
// Kernel 1 (fused): per block —
//   (0) front-batch the 8 X-tile LDG.128 into registers (MLP 8),
//   (a) zero a 2048-float4 slice of the output accumulation area,  } hide X
//   (b) build this branch's reparameterized W into fp16 smem,      } latency
//   (c) convert/store the prefetched X tile to fp16 smem,
//   (d) HMMA GEMM: 128x64 tile, 8 warps, mma.m16n8k16, f32 accum,
//       epilogue -> fp16 support tensors.
//   branch 0: sup_mean = mean @ W_mean ; branch 1: sup_var = (std^2) @ W_var
// ---------------------------------------------------------------------------
__global__ __launch_bounds__(256) void gemm_fused_kernel(
    const float* __restrict__ mean, const float* __restrict__ stdv,
    const float* __restrict__ mu_m, const float* __restrict__ ls_m,
    const float* __restrict__ eps_m,
    const float* __restrict__ mu_s, const float* __restrict__ ls_s,
    const float* __restrict__ eps_s,
    float* __restrict__ out_base)
{
    __shared__ __half sX[128 * PITCH];   // 18432 B
    __shared__ __half sW[CH * PITCH];    //  9216 B

    int branch = blockIdx.y;
    int row0 = blockIdx.x * 128;
    int tid = threadIdx.x;
    int bid = blockIdx.x + GX * branch;  // 0..781

    // (0) prefetch X: 8 independent LDG.128, issued before anything else
    const float4* in4 = (const float4*)(branch ? stdv : mean);
    float4 xv[8];
    #pragma unroll
    for (int t = 0; t < 8; t++) {
        int i = t * 256 + tid;          // 0..2047
        int c4 = i & 15, r = i >> 4;
        int node = row0 + r;
        xv[t] = make_float4(0.f, 0.f, 0.f, 0.f);
        if (node < N_NODES) xv[t] = in4[node * CH4 + c4];
    }

    // (a) zero 2048 float4 of the output accumulation area (independent work)
    {
        float4* out4 = (float4*)out_base;
        float4 z = make_float4(0.f, 0.f, 0.f, 0.f);
        #pragma unroll
        for (int t = 0; t < 8; t++) {
            int i = bid * 2048 + t * 256 + tid;
            if (i < ZERO_FLOAT4) out4[i] = z;
        }
    }

    // (b) build this branch's W into fp16 smem (independent work; L2-resident)
    {
        const float* mu  = branch ? mu_s  : mu_m;
        const float* ls  = branch ? ls_s  : ls_m;
        const float* eps = branch ? eps_s : eps_m;
        #pragma unroll
        for (int t = 0; t < 16; t++) {
            int i = t * 256 + tid;           // 0..4095
            int k = i >> 6, c = i & 63;
            float wv = mu[i] + eps[i] * expf(ls[i]);
            sW[k * PITCH + c] = __float2half_rn(wv);
        }
    }

    // (c) convert and store the prefetched X tile
    {
        #pragma unroll
        for (int t = 0; t < 8; t++) {
            int i = t * 256 + tid;
            int c4 = i & 15, r = i >> 4;
            float4 v = xv[t];
            if (branch) { v.x *= v.x; v.y *= v.y; v.z *= v.z; v.w *= v.w; }
            __half2 h0 = __floats2half2_rn(v.x, v.y);
            __half2 h1 = __floats2half2_rn(v.z, v.w);
            *(__half2*)&sX[r * PITCH + c4 * 4]     = h0;
            *(__half2*)&sX[r * PITCH + c4 * 4 + 2] = h1;
        }
    }
    __syncthreads();

    int w = tid >> 5, lane = tid & 31;

    float acc[8][4];
    #pragma unroll
    for (int nt = 0; nt < 8; nt++)
        #pragma unroll
        for (int c = 0; c < 4; c++) acc[nt][c] = 0.f;

    #pragma unroll
    for (int kk = 0; kk < 4; kk++) {
        // A fragment: 16x16 at rows w*16, k-cols kk*16 (ldmatrix.x4)
        unsigned a0, a1, a2, a3;
        {
            int r = lane & 15, c8 = (lane >> 4) * 8;
            unsigned aaddr = (unsigned)__cvta_generic_to_shared(
                &sX[(w * 16 + r) * PITCH + kk * 16 + c8]);
            asm volatile(
                "ldmatrix.sync.aligned.m8n8.x4.shared.b16 {%0,%1,%2,%3}, [%4];"
                : "=r"(a0), "=r"(a1), "=r"(a2), "=r"(a3) : "r"(aaddr));
        }
        #pragma unroll
        for (int nt = 0; nt < 8; nt++) {
            // B fragment: 16x8 at k-rows kk*16, n-cols nt*8 (ldmatrix.x2.trans)
            unsigned b0, b1;
            {
                unsigned baddr = (unsigned)__cvta_generic_to_shared(
                    &sW[(kk * 16 + (lane & 15)) * PITCH + nt * 8]);
                asm volatile(
                    "ldmatrix.sync.aligned.m8n8.x2.trans.shared.b16 {%0,%1}, [%2];"
                    : "=r"(b0), "=r"(b1) : "r"(baddr));
            }
            asm volatile(
                "mma.sync.aligned.m16n8k16.row.col.f32.f16.f16.f32 "
                "{%0,%1,%2,%3}, {%4,%5,%6,%7}, {%8,%9}, {%0,%1,%2,%3};"
                : "+f"(acc[nt][0]), "+f"(acc[nt][1]),
                  "+f"(acc[nt][2]), "+f"(acc[nt][3])
                : "r"(a0), "r"(a1), "r"(a2), "r"(a3), "r"(b0), "r"(b1));
        }
    }

    // epilogue: acc -> fp16 support tensor
    unsigned* suph = (unsigned*)g_suph[branch];
    int g = lane >> 2, tg = lane & 3;
    int node0 = row0 + w * 16 + g;
    int node1 = node0 + 8;
    #pragma unroll
    for (int nt = 0; nt < 8; nt++) {
        __half2 h0 = __floats2half2_rn(acc[nt][0], acc[nt][1]);
        __half2 h1 = __floats2half2_rn(acc[nt][2], acc[nt][3]);
        int cidx = nt * 4 + tg;              // uint index within 32-uint row
        if (node0 < N_NODES) suph[node0 * 32 + cidx] = *(unsigned*)&h0;
        if (node1 < N_NODES) suph[node1 * 32 + cidx] = *(unsigned*)&h1;
    }
}

// ---------------------------------------------------------------------------
// Kernel 2: edge scatter, TWO edges + both branches per thread.
// fp16 gathers, fp32 vector reductions out.
// ---------------------------------------------------------------------------
__global__ __launch_bounds__(512) void scatter_kernel(
    const int* __restrict__ ei, const float* __restrict__ ew,
    float* __restrict__ out_mean, float* __restrict__ out_var)
{
    int idx = blockIdx.x * 512 + threadIdx.x;          // < HALF_E*16 = 6.4M
    int j = idx & 15;                                  // chunk within row
    int e0 = idx >> 4;                                 // 0..HALF_E-1
    int e1 = e0 + HALF_E;

    // front-batched meta loads (6 independent)
    int   s0 = __ldg(&ei[e0]);
    int   s1 = __ldg(&ei[e1]);
    int   d0 = __ldg(&ei[N_EDGES + e0]);
    int   d1 = __ldg(&ei[N_EDGES + e1]);
    float w0 = __ldg(&ew[e0]);
    float w1 = __ldg(&ew[e1]);

    // 4 independent fp16 gathers (8B each; warp-coalesced 128B rows)
    uint2 m0h = __ldg(&g_suph[0][s0 * CH4 + j]);
    uint2 m1h = __ldg(&g_suph[0][s1 * CH4 + j]);
    uint2 v0h = __ldg(&g_suph[1][s0 * CH4 + j]);
    uint2 v1h = __ldg(&g_suph[1][s1 * CH4 + j]);

    float q0 = w0 * w0, q1 = w1 * w1;

    float2 m0a = __half22float2(*(__half2*)&m0h.x);
    float2 m0b = __half22float2(*(__half2*)&m0h.y);
    float2 m1a = __half22float2(*(__half2*)&m1h.x);
    float2 m1b = __half22float2(*(__half2*)&m1h.y);
    float2 v0a = __half22float2(*(__half2*)&v0h.x);
    float2 v0b = __half22float2(*(__half2*)&v0h.y);
    float2 v1a = __half22float2(*(__half2*)&v1h.x);
    float2 v1b = __half22float2(*(__half2*)&v1h.y);

    float* am0 = out_mean + d0 * CH + j * 4;
    float* av0 = out_var  + d0 * CH + j * 4;
    float* am1 = out_mean + d1 * CH + j * 4;
    float* av1 = out_var  + d1 * CH + j * 4;

    asm volatile("red.global.add.v4.f32 [%0], {%1, %2, %3, %4};"
                 :: "l"(am0), "f"(m0a.x * w0), "f"(m0a.y * w0), "f"(m0b.x * w0), "f"(m0b.y * w0)
                 : "memory");
    asm volatile("red.global.add.v4.f32 [%0], {%1, %2, %3, %4};"
                 :: "l"(av0), "f"(v0a.x * q0), "f"(v0a.y * q0), "f"(v0b.x * q0), "f"(v0b.y * q0)
                 : "memory");
    asm volatile("red.global.add.v4.f32 [%0], {%1, %2, %3, %4};"
                 :: "l"(am1), "f"(m1a.x * w1), "f"(m1a.y * w1), "f"(m1b.x * w1), "f"(m1b.y * w1)
                 : "memory");
    asm volatile("red.global.add.v4.f32 [%0], {%1, %2, %3, %4};"
                 :: "l"(av1), "f"(v1a.x * q1), "f"(v1a.y * q1), "f"(v1b.x * q1), "f"(v1b.y * q1)
                 : "memory");
}

// ---------------------------------------------------------------------------
// Kernel 3: finalize std (R10 form) + KL in block 0 (hides in multi-wave grid).
// ---------------------------------------------------------------------------
__global__ __launch_bounds__(256) void finalize_kernel(
    float4* __restrict__ out_var4,
    const float* __restrict__ mu_m, const float* __restrict__ ls_m,
    const float* __restrict__ mu_s, const float* __restrict__ ls_s,
    float* __restrict__ kl_out)
{
    if (blockIdx.x == 0) {
        __shared__ float sred[256];
        int tid = threadIdx.x;
        float acc = 0.f;
        for (int i = tid; i < CH * CH; i += 256) {
            float lm = ls_m[i], mm = mu_m[i];
            acc += 0.5f * (expf(2.f * lm) + mm * mm - 2.f * lm - 1.f);
            float lv = ls_s[i], ms = mu_s[i];
            acc += 0.5f * (expf(2.f * lv) + ms * ms - 2.f * lv - 1.f);
        }
        sred[tid] = acc;
        __syncthreads();
        for (int s = 128; s > 0; s >>= 1) {
            if (tid < s) sred[tid] += sred[tid + s];
            __syncthreads();
        }
        if (tid == 0) kl_out[0] = sred[0];
    }

    int base = blockIdx.x * 1024 + threadIdx.x;
    #pragma unroll
    for (int t = 0; t < 4; t++) {
        int i = base + t * 256;
        if (i < OUT_ELEMS / 4) {
            float4 x = out_var4[i];
            x.x = __fsqrt_rn(__expf(x.x) + 1e-6f);
            x.y = __fsqrt_rn(__expf(x.y) + 1e-6f);
            x.z = __fsqrt_rn(__expf(x.z) + 1e-6f);
            x.w = __fsqrt_rn(__expf(x.w) + 1e-6f);
            out_var4[i] = x;
        }
    }
}

// ---------------------------------------------------------------------------
extern "C" void kernel_launch(void* const* d_in, const int* in_sizes, int n_in,
                              void* d_out, int out_size)
{
    const float* mean  = (const float*)d_in[0];   // [50000, 64]
    const float* stdv  = (const float*)d_in[1];   // [50000, 64]
    const int*   ei    = (const int*)  d_in[2];   // [2, 800000]
    const float* ew    = (const float*)d_in[3];   // [800000]
    const float* mu_m  = (const float*)d_in[4];
    const float* ls_m  = (const float*)d_in[5];
    const float* eps_m = (const float*)d_in[6];
    const float* mu_s  = (const float*)d_in[7];
    const float* ls_s  = (const float*)d_in[8];
    const float* eps_s = (const float*)d_in[9];

    float* out_mean = (float*)d_out;                   // [50000*64]
    float* out_var  = out_mean + OUT_ELEMS;            // [50000*64]
    float* kl_out   = out_mean + 2 * OUT_ELEMS;        // scalar

    // 1) fused: X-prefetch + zero + W build + dual HMMA GEMM
    {
        dim3 grid(GX, 2);
        gemm_fused_kernel<<<grid, 256>>>(mean, stdv,
                                         mu_m, ls_m, eps_m,
                                         mu_s, ls_s, eps_s,
                                         out_mean);
    }
    // 2) edge scatter (2 edges x both branches per thread)
    {
        int total = HALF_E * 16;                       // 6,400,000 threads
        scatter_kernel<<<total / 512, 512>>>(ei, ew, out_mean, out_var);
    }
    // 3) finalize std + KL
    finalize_kernel<<<782, 256>>>((float4*)out_var,
                                  mu_m, ls_m, mu_s, ls_s, kl_out);
}

// round 17
// speedup vs baseline: 1.0519x; 1.0519x over previous
#include <cuda_runtime.h>
#include <cuda_fp16.h>
#include <cstdint>

#define N_NODES 50000
#define N_EDGES 800000
#define QUART_E (N_EDGES / 4)
#define CH 64
#define CH4 16
#define OUT_ELEMS (N_NODES * CH)
#define GX 391                            // ceil(50000/128)
#define ZERO_FLOAT4 (OUT_ELEMS * 2 / 4)   // 1,600,000
#define PITCH 72                          // smem pitch in halves (conflict-free LDSM)

// ---- scratch (device globals; no allocation allowed) ----
// support tensors in fp16: [branch][node*16 + chunk], chunk = 4 halves (8B)
__device__ uint2 g_suph[2][N_NODES * CH4];

// ---------------------------------------------------------------------------
// Kernel 1 (fused, R10 exact): per block —
//   (a) zero a 2048-float4 slice of the output accumulation area,
//   (b) build this branch's reparameterized W into fp16 smem,
//   (c) block (0,0) reduces KL for both branches,
//   (d) HMMA GEMM: 128x64 tile, 8 warps, mma.m16n8k16, f32 accum,
//       epilogue -> fp16 support tensors.
// ---------------------------------------------------------------------------
__global__ __launch_bounds__(256) void gemm_fused_kernel(
    const float* __restrict__ mean, const float* __restrict__ stdv,
    const float* __restrict__ mu_m, const float* __restrict__ ls_m,
    const float* __restrict__ eps_m,
    const float* __restrict__ mu_s, const float* __restrict__ ls_s,
    const float* __restrict__ eps_s,
    float* __restrict__ out_base, float* __restrict__ kl_out)
{
    __shared__ __half sX[128 * PITCH];   // 18432 B
    __shared__ __half sW[CH * PITCH];    //  9216 B

    int branch = blockIdx.y;
    int row0 = blockIdx.x * 128;
    int tid = threadIdx.x;
    int bid = blockIdx.x + GX * branch;  // 0..781

    // (a) zero 2048 float4 of the output accumulation area
    {
        float4* out4 = (float4*)out_base;
        float4 z = make_float4(0.f, 0.f, 0.f, 0.f);
        #pragma unroll
        for (int t = 0; t < 8; t++) {
            int i = bid * 2048 + t * 256 + tid;
            if (i < ZERO_FLOAT4) out4[i] = z;
        }
    }

    // (b) build this branch's W into fp16 smem
    {
        const float* mu  = branch ? mu_s  : mu_m;
        const float* ls  = branch ? ls_s  : ls_m;
        const float* eps = branch ? eps_s : eps_m;
        #pragma unroll
        for (int t = 0; t < 16; t++) {
            int i = t * 256 + tid;           // 0..4095
            int k = i >> 6, c = i & 63;
            float wv = mu[i] + eps[i] * expf(ls[i]);
            sW[k * PITCH + c] = __float2half_rn(wv);
        }
    }

    // (c) KL: block (0,0) only, both branches
    if (blockIdx.x == 0 && branch == 0) {
        __shared__ float sred[256];
        float acc = 0.f;
        for (int i = tid; i < CH * CH; i += 256) {
            float lm = ls_m[i], mm = mu_m[i];
            acc += 0.5f * (expf(2.f * lm) + mm * mm - 2.f * lm - 1.f);
            float lv = ls_s[i], ms = mu_s[i];
            acc += 0.5f * (expf(2.f * lv) + ms * ms - 2.f * lv - 1.f);
        }
        sred[tid] = acc;
        __syncthreads();
        for (int s = 128; s > 0; s >>= 1) {
            if (tid < s) sred[tid] += sred[tid + s];
            __syncthreads();
        }
        if (tid == 0) kl_out[0] = sred[0];
    }

    // stage X (128x64): 2048 float4 chunks; 16 lanes per row (coalesced)
    const float4* in4 = (const float4*)(branch ? stdv : mean);
    {
        #pragma unroll
        for (int t = 0; t < 8; t++) {
            int i = t * 256 + tid;          // 0..2047
            int c4 = i & 15, r = i >> 4;
            int node = row0 + r;
            float4 v = make_float4(0.f, 0.f, 0.f, 0.f);
            if (node < N_NODES) v = in4[node * CH4 + c4];
            if (branch) { v.x *= v.x; v.y *= v.y; v.z *= v.z; v.w *= v.w; }
            __half2 h0 = __floats2half2_rn(v.x, v.y);
            __half2 h1 = __floats2half2_rn(v.z, v.w);
            *(__half2*)&sX[r * PITCH + c4 * 4]     = h0;
            *(__half2*)&sX[r * PITCH + c4 * 4 + 2] = h1;
        }
    }
    __syncthreads();

    int w = tid >> 5, lane = tid & 31;

    float acc[8][4];
    #pragma unroll
    for (int nt = 0; nt < 8; nt++)
        #pragma unroll
        for (int c = 0; c < 4; c++) acc[nt][c] = 0.f;

    #pragma unroll
    for (int kk = 0; kk < 4; kk++) {
        unsigned a0, a1, a2, a3;
        {
            int r = lane & 15, c8 = (lane >> 4) * 8;
            unsigned aaddr = (unsigned)__cvta_generic_to_shared(
                &sX[(w * 16 + r) * PITCH + kk * 16 + c8]);
            asm volatile(
                "ldmatrix.sync.aligned.m8n8.x4.shared.b16 {%0,%1,%2,%3}, [%4];"
                : "=r"(a0), "=r"(a1), "=r"(a2), "=r"(a3) : "r"(aaddr));
        }
        #pragma unroll
        for (int nt = 0; nt < 8; nt++) {
            unsigned b0, b1;
            {
                unsigned baddr = (unsigned)__cvta_generic_to_shared(
                    &sW[(kk * 16 + (lane & 15)) * PITCH + nt * 8]);
                asm volatile(
                    "ldmatrix.sync.aligned.m8n8.x2.trans.shared.b16 {%0,%1}, [%2];"
                    : "=r"(b0), "=r"(b1) : "r"(baddr));
            }
            asm volatile(
                "mma.sync.aligned.m16n8k16.row.col.f32.f16.f16.f32 "
                "{%0,%1,%2,%3}, {%4,%5,%6,%7}, {%8,%9}, {%0,%1,%2,%3};"
                : "+f"(acc[nt][0]), "+f"(acc[nt][1]),
                  "+f"(acc[nt][2]), "+f"(acc[nt][3])
                : "r"(a0), "r"(a1), "r"(a2), "r"(a3), "r"(b0), "r"(b1));
        }
    }

    // epilogue: acc -> fp16 support tensor
    unsigned* suph = (unsigned*)g_suph[branch];
    int g = lane >> 2, tg = lane & 3;
    int node0 = row0 + w * 16 + g;
    int node1 = node0 + 8;
    #pragma unroll
    for (int nt = 0; nt < 8; nt++) {
        __half2 h0 = __floats2half2_rn(acc[nt][0], acc[nt][1]);
        __half2 h1 = __floats2half2_rn(acc[nt][2], acc[nt][3]);
        int cidx = nt * 4 + tg;
        if (node0 < N_NODES) suph[node0 * 32 + cidx] = *(unsigned*)&h0;
        if (node1 < N_NODES) suph[node1 * 32 + cidx] = *(unsigned*)&h1;
    }
}

// ---------------------------------------------------------------------------
// Kernel 2: edge scatter, FOUR edges + both branches per thread.
// 12 front-batched meta loads, 8 independent fp16 gathers (deep MLP),
// 8 fp32 vector reductions out.
// ---------------------------------------------------------------------------
__global__ __launch_bounds__(512) void scatter_kernel(
    const int* __restrict__ ei, const float* __restrict__ ew,
    float* __restrict__ out_mean, float* __restrict__ out_var)
{
    int idx = blockIdx.x * 512 + threadIdx.x;          // < QUART_E*16 = 3.2M
    int j = idx & 15;                                  // chunk within row
    int eb = idx >> 4;                                 // 0..QUART_E-1

    int e[4];
    #pragma unroll
    for (int k = 0; k < 4; k++) e[k] = eb + k * QUART_E;

    // front-batched meta loads (12 independent)
    int s[4], d[4];
    float wv[4];
    #pragma unroll
    for (int k = 0; k < 4; k++) s[k] = __ldg(&ei[e[k]]);
    #pragma unroll
    for (int k = 0; k < 4; k++) d[k] = __ldg(&ei[N_EDGES + e[k]]);
    #pragma unroll
    for (int k = 0; k < 4; k++) wv[k] = __ldg(&ew[e[k]]);

    // 8 independent fp16 gathers (8B each; warp-coalesced 128B rows)
    uint2 mh[4], vh[4];
    #pragma unroll
    for (int k = 0; k < 4; k++) mh[k] = __ldg(&g_suph[0][s[k] * CH4 + j]);
    #pragma unroll
    for (int k = 0; k < 4; k++) vh[k] = __ldg(&g_suph[1][s[k] * CH4 + j]);

    #pragma unroll
    for (int k = 0; k < 4; k++) {
        float wq = wv[k];
        float qq = wq * wq;
        float2 ma = __half22float2(*(__half2*)&mh[k].x);
        float2 mb = __half22float2(*(__half2*)&mh[k].y);
        float2 va = __half22float2(*(__half2*)&vh[k].x);
        float2 vb = __half22float2(*(__half2*)&vh[k].y);
        float* am = out_mean + d[k] * CH + j * 4;
        float* av = out_var  + d[k] * CH + j * 4;
        asm volatile("red.global.add.v4.f32 [%0], {%1, %2, %3, %4};"
                     :: "l"(am), "f"(ma.x * wq), "f"(ma.y * wq),
                        "f"(mb.x * wq), "f"(mb.y * wq)
                     : "memory");
        asm volatile("red.global.add.v4.f32 [%0], {%1, %2, %3, %4};"
                     :: "l"(av), "f"(va.x * qq), "f"(va.y * qq),
                        "f"(vb.x * qq), "f"(vb.y * qq)
                     : "memory");
    }
}

// ---------------------------------------------------------------------------
// Kernel 3: finalize std: std = sqrt(exp(log_var)+1e-6), fast-math MUFU.
// ---------------------------------------------------------------------------
__global__ __launch_bounds__(256) void finalize_kernel(float4* __restrict__ out_var4) {
    int base = blockIdx.x * 1024 + threadIdx.x;
    #pragma unroll
    for (int t = 0; t < 4; t++) {
        int i = base + t * 256;
        if (i < OUT_ELEMS / 4) {
            float4 x = out_var4[i];
            x.x = __fsqrt_rn(__expf(x.x) + 1e-6f);
            x.y = __fsqrt_rn(__expf(x.y) + 1e-6f);
            x.z = __fsqrt_rn(__expf(x.z) + 1e-6f);
            x.w = __fsqrt_rn(__expf(x.w) + 1e-6f);
            out_var4[i] = x;
        }
    }
}

// ---------------------------------------------------------------------------
extern "C" void kernel_launch(void* const* d_in, const int* in_sizes, int n_in,
                              void* d_out, int out_size)
{
    const float* mean  = (const float*)d_in[0];   // [50000, 64]
    const float* stdv  = (const float*)d_in[1];   // [50000, 64]
    const int*   ei    = (const int*)  d_in[2];   // [2, 800000]
    const float* ew    = (const float*)d_in[3];   // [800000]
    const float* mu_m  = (const float*)d_in[4];
    const float* ls_m  = (const float*)d_in[5];
    const float* eps_m = (const float*)d_in[6];
    const float* mu_s  = (const float*)d_in[7];
    const float* ls_s  = (const float*)d_in[8];
    const float* eps_s = (const float*)d_in[9];

    float* out_mean = (float*)d_out;                   // [50000*64]
    float* out_var  = out_mean + OUT_ELEMS;            // [50000*64]
    float* kl_out   = out_mean + 2 * OUT_ELEMS;        // scalar

    // 1) fused: zero + W build + KL + dual HMMA GEMM (R10 exact)
    {
        dim3 grid(GX, 2);
        gemm_fused_kernel<<<grid, 256>>>(mean, stdv,
                                         mu_m, ls_m, eps_m,
                                         mu_s, ls_s, eps_s,
                                         out_mean, kl_out);
    }
    // 2) edge scatter (4 edges x both branches per thread)
    {
        int total = QUART_E * 16;                      // 3,200,000 threads
        scatter_kernel<<<total / 512, 512>>>(ei, ew, out_mean, out_var);
    }
    // 3) finalize std
    finalize_kernel<<<782, 256>>>((float4*)out_var);
}